// round 14
// baseline (speedup 1.0000x reference)
#include <cuda_runtime.h>
#include <cuda_bf16.h>
#include <cstdint>

#define BATCH      8192
#define STATE_DIM  322
#define N_NODES    256
#define ENTRIES    27
#define ACTION     4096

// Intermediates: y as bf16 [BATCH][256] (4 MB), Wf as bf16 [4096][256] (2 MB)
__device__ __nv_bfloat16 g_y [BATCH  * N_NODES];
__device__ __nv_bfloat16 g_wf[ACTION * N_NODES];

__device__ __forceinline__ uint32_t smem_u32(const void* p) {
    uint32_t a;
    asm("{ .reg .u64 t; cvta.to.shared.u64 t, %1; cvt.u32.u64 %0, t; }" : "=r"(a) : "l"(p));
    return a;
}
#define CP_ASYNC16(dst, src) \
    asm volatile("cp.async.cg.shared.global [%0], [%1], 16;" :: "r"(dst), "l"(src))
#define CP_COMMIT()  asm volatile("cp.async.commit_group;" ::: "memory")
#define CP_WAIT(N)   asm volatile("cp.async.wait_group %0;" :: "n"(N) : "memory")

__device__ __forceinline__ void ldmx4(uint32_t* r, uint32_t addr) {
    asm volatile("ldmatrix.sync.aligned.m8n8.x4.shared.b16 {%0,%1,%2,%3}, [%4];"
                 : "=r"(r[0]), "=r"(r[1]), "=r"(r[2]), "=r"(r[3]) : "r"(addr));
}
__device__ __forceinline__ void mma_bf16(float c[4], const uint32_t a[4],
                                         uint32_t b0, uint32_t b1) {
    asm volatile(
        "mma.sync.aligned.m16n8k16.row.col.f32.bf16.bf16.f32 "
        "{%0,%1,%2,%3}, {%4,%5,%6,%7}, {%8,%9}, {%0,%1,%2,%3};"
        : "+f"(c[0]), "+f"(c[1]), "+f"(c[2]), "+f"(c[3])
        : "r"(a[0]), "r"(a[1]), "r"(a[2]), "r"(a[3]), "r"(b0), "r"(b1));
}
__device__ __forceinline__ float tanh_approx(float x) {
    float r;
    asm("tanh.approx.f32 %0, %1;" : "=f"(r) : "f"(x));
    return r;
}

// ---------------------------------------------------------------------------
// Kernel 1: fused prep (node forward + Wf bf16 convert)
// ---------------------------------------------------------------------------
#define R_PER_BLK  16
#define NODE_BLKS  (BATCH / R_PER_BLK)          // 512
#define CONV_BLKS  (ACTION * N_NODES / 1024)    // 1024

__global__ __launch_bounds__(256) void prep_kernel(
    const float* __restrict__ state, const float* __restrict__ W,
    const float* __restrict__ b,     const int*   __restrict__ idx,
    const float* __restrict__ Wf)
{
    if (blockIdx.x >= NODE_BLKS) {
        const int i = ((blockIdx.x - NODE_BLKS) * 256 + threadIdx.x) * 4;
        float4 v = *(const float4*)(Wf + i);
        __nv_bfloat162* p = (__nv_bfloat162*)(g_wf + i);
        p[0] = __floats2bfloat162_rn(v.x, v.y);
        p[1] = __floats2bfloat162_rn(v.z, v.w);
        return;
    }
    __shared__ float s[R_PER_BLK * STATE_DIM];
    const int t = threadIdx.x, row0 = blockIdx.x * R_PER_BLK;
    const float* sp = state + (long)row0 * STATE_DIM;
    for (int i = t; i < R_PER_BLK * STATE_DIM; i += 256) s[i] = sp[i];

    float w[ENTRIES]; int ix[ENTRIES];
#pragma unroll
    for (int e = 0; e < ENTRIES; e++) { w[e] = W[t*ENTRIES+e]; ix[e] = idx[t*ENTRIES+e]; }
    const float bb = b[t];
    __syncthreads();
#pragma unroll 4
    for (int r = 0; r < R_PER_BLK; r++) {
        const float* sr = s + r * STATE_DIM;
        float acc = bb;
#pragma unroll
        for (int e = 0; e < ENTRIES; e++) acc = fmaf(sr[ix[e]], w[e], acc);
        g_y[(long)(row0 + r) * N_NODES + t] = __float2bfloat16(tanh_approx(acc));
    }
}

// ---------------------------------------------------------------------------
// Kernel 2: out = 500*sigmoid(y @ Wf^T), bf16 mma.sync.m16n8k16.
// Grid 32(n) x 32(m-strips). CTA: B tile 128n x 256k RESIDENT in swizzled
// smem (64 KB, loaded once); 2 m-tiles of 128 streamed via 3-stage A pipeline
// (depth-2 lookahead -> ONE __syncthreads per K-iteration). 256 threads,
// 8 warps 2m x 4n, warp tile 64x32. smem 112 KB -> 2 CTAs/SM.
// XOR swizzle ((row&7)<<4) keeps every ldmatrix phase on 32 distinct banks.
// ---------------------------------------------------------------------------
#define BK       64
#define A_STAGE  16384                 // 128 rows x 128 B, swizzled
#define NSTAGE   3
#define B_OFF    (NSTAGE * A_STAGE)    // 49152
#define B_ROWB   512                   // 256 bf16 per row, swizzled
#define SMEM_SZ  (B_OFF + 128 * B_ROWB) // 114688 = 112 KB

__global__ __launch_bounds__(256, 2) void gemm_sig_kernel(float* __restrict__ out)
{
    extern __shared__ char smem[];
    const uint32_t sb = smem_u32(smem);
    const int tid    = threadIdx.x;
    const int lane   = tid & 31;
    const int wid    = tid >> 5;
    const int warp_m = wid >> 2;        // 0..1
    const int warp_n = wid & 3;         // 0..3
    const int n0      = blockIdx.x * 128;
    const int m_strip = blockIdx.y * 256;

    const __nv_bfloat16* gB = g_wf + (size_t)n0 * N_NODES;

    // ---- prologue ----
    // group 0: B (4096 x 16B) + A chunk0 ; group 1: A chunk1
#pragma unroll
    for (int i = 0; i < 16; i++) {
        const int e = tid + i * 256, r = e >> 5, c = e & 31;
        CP_ASYNC16(sb + B_OFF + r * B_ROWB + ((c * 16) ^ ((r & 7) << 4)),
                   (const void*)(gB + (size_t)r * N_NODES + c * 8));
    }
    {
        const __nv_bfloat16* gA = g_y + (size_t)m_strip * N_NODES;
#pragma unroll
        for (int i = 0; i < 4; i++) {
            const int e = tid + i * 256, r = e >> 3, c = e & 7;
            CP_ASYNC16(sb + r * 128 + ((c * 16) ^ ((r & 7) << 4)),
                       (const void*)(gA + (size_t)r * N_NODES + c * 8));
        }
    }
    CP_COMMIT();
    {
        const __nv_bfloat16* gA = g_y + (size_t)m_strip * N_NODES + BK;
#pragma unroll
        for (int i = 0; i < 4; i++) {
            const int e = tid + i * 256, r = e >> 3, c = e & 7;
            CP_ASYNC16(sb + A_STAGE + r * 128 + ((c * 16) ^ ((r & 7) << 4)),
                       (const void*)(gA + (size_t)r * N_NODES + c * 8));
        }
    }
    CP_COMMIT();

    // per-thread fragment row bases (swizzle XOR term = (lane&7)<<4 for all)
    const uint32_t xr   = (lane & 7) << 4;
    const uint32_t hi_a = (lane >> 4) * 16;         // A: lanes 16-31 -> +16B in k
    const uint32_t hi_b = ((lane >> 3) & 1) * 16;   // B: x4 second-half k offset

    uint32_t a_row[4];
#pragma unroll
    for (int mt = 0; mt < 4; mt++)
        a_row[mt] = sb + (warp_m * 64 + mt * 16 + (lane & 15)) * 128;
    uint32_t b_row[2];
#pragma unroll
    for (int p = 0; p < 2; p++)
        b_row[p] = sb + B_OFF
                 + (warp_n * 32 + p * 16 + ((lane >> 4) & 1) * 8 + (lane & 7)) * B_ROWB;

    const int frow = lane >> 2, fcol = lane & 3;
    float acc[4][4][4] = {};

#pragma unroll
    for (int t = 0; t < 8; t++) {             // 2 m-tiles x 4 K-chunks
        if (t < 7) CP_WAIT(1); else CP_WAIT(0);
        __syncthreads();

        // prefetch A chunk t+2 into stage (t+2)%3 (freed at iteration t-1)
        if (t < 6) {
            const int nt_ = t + 2;
            const __nv_bfloat16* gA =
                g_y + (size_t)(m_strip + (nt_ >> 2) * 128) * N_NODES + (nt_ & 3) * BK;
            const uint32_t dst = sb + (nt_ % NSTAGE) * A_STAGE;
#pragma unroll
            for (int i = 0; i < 4; i++) {
                const int e = tid + i * 256, r = e >> 3, c = e & 7;
                CP_ASYNC16(dst + r * 128 + ((c * 16) ^ ((r & 7) << 4)),
                           (const void*)(gA + (size_t)r * N_NODES + c * 8));
            }
            CP_COMMIT();
        }

        const uint32_t soff  = (t % NSTAGE) * A_STAGE;
        const uint32_t bkoff = (t & 3) * 128;       // B k-byte offset for this chunk
#pragma unroll
        for (int kc = 0; kc < 4; kc++) {
            uint32_t a[4][4], bp[2][4];
            const uint32_t ka = (kc * 32 + hi_a) ^ xr;
            const uint32_t kb = (kc * 32 + hi_b) ^ xr;
#pragma unroll
            for (int mt = 0; mt < 4; mt++) ldmx4(a[mt], a_row[mt] + soff + ka);
#pragma unroll
            for (int p = 0; p < 2; p++)    ldmx4(bp[p], b_row[p] + bkoff + kb);
#pragma unroll
            for (int mt = 0; mt < 4; mt++)
#pragma unroll
                for (int nt = 0; nt < 4; nt++)
                    mma_bf16(acc[mt][nt], a[mt],
                             bp[nt >> 1][(nt & 1) * 2], bp[nt >> 1][(nt & 1) * 2 + 1]);
        }

        // end of an m-tile: epilogue (overlaps with next tile's in-flight loads)
        if ((t & 3) == 3) {
            const int m_base = m_strip + (t >> 2) * 128 + warp_m * 64;
#pragma unroll
            for (int mt = 0; mt < 4; mt++) {
                const int m = m_base + mt * 16 + frow;
#pragma unroll
                for (int nt = 0; nt < 4; nt++) {
                    const int n = n0 + warp_n * 32 + nt * 8 + 2 * fcol;
                    float2 o0, o1;
                    o0.x = __fdividef(500.0f, 1.0f + __expf(-acc[mt][nt][0]));
                    o0.y = __fdividef(500.0f, 1.0f + __expf(-acc[mt][nt][1]));
                    o1.x = __fdividef(500.0f, 1.0f + __expf(-acc[mt][nt][2]));
                    o1.y = __fdividef(500.0f, 1.0f + __expf(-acc[mt][nt][3]));
                    *(float2*)&out[(size_t)m * ACTION + n]       = o0;
                    *(float2*)&out[(size_t)(m + 8) * ACTION + n] = o1;
#pragma unroll
                    for (int q = 0; q < 4; q++) acc[mt][nt][q] = 0.0f;
                }
            }
        }
    }
}

// ---------------------------------------------------------------------------
extern "C" void kernel_launch(void* const* d_in, const int* in_sizes, int n_in,
                              void* d_out, int out_size)
{
    const float* state = (const float*)d_in[0];
    const float* W     = (const float*)d_in[1];
    const float* b     = (const float*)d_in[2];
    const float* Wf    = (const float*)d_in[3];
    const int*   idx   = (const int*)  d_in[4];
    float*       out   = (float*)d_out;

    cudaFuncSetAttribute(gemm_sig_kernel,
                         cudaFuncAttributeMaxDynamicSharedMemorySize, SMEM_SZ);

    prep_kernel<<<NODE_BLKS + CONV_BLKS, 256>>>(state, W, b, idx, Wf);

    dim3 grid(ACTION / 128, BATCH / 256);
    gemm_sig_kernel<<<grid, 256, SMEM_SZ>>>(out);
}

// round 15
// speedup vs baseline: 1.4052x; 1.4052x over previous
#include <cuda_runtime.h>
#include <cuda_bf16.h>
#include <cstdint>

#define BATCH      8192
#define STATE_DIM  322
#define N_NODES    256
#define ENTRIES    27
#define ACTION     4096

// Intermediates: y as bf16 [BATCH][256] (4 MB), Wf as bf16 [4096][256] (2 MB)
__device__ __nv_bfloat16 g_y [BATCH  * N_NODES];
__device__ __nv_bfloat16 g_wf[ACTION * N_NODES];

__device__ __forceinline__ uint32_t smem_u32(const void* p) {
    uint32_t a;
    asm("{ .reg .u64 t; cvta.to.shared.u64 t, %1; cvt.u32.u64 %0, t; }" : "=r"(a) : "l"(p));
    return a;
}
#define CP_ASYNC16(dst, src) \
    asm volatile("cp.async.cg.shared.global [%0], [%1], 16;" :: "r"(dst), "l"(src))
#define CP_COMMIT()  asm volatile("cp.async.commit_group;" ::: "memory")
#define CP_WAIT(N)   asm volatile("cp.async.wait_group %0;" :: "n"(N) : "memory")

__device__ __forceinline__ void ldmx4(uint32_t* r, uint32_t addr) {
    asm volatile("ldmatrix.sync.aligned.m8n8.x4.shared.b16 {%0,%1,%2,%3}, [%4];"
                 : "=r"(r[0]), "=r"(r[1]), "=r"(r[2]), "=r"(r[3]) : "r"(addr));
}
__device__ __forceinline__ void mma_bf16(float c[4], const uint32_t a[4],
                                         uint32_t b0, uint32_t b1) {
    asm volatile(
        "mma.sync.aligned.m16n8k16.row.col.f32.bf16.bf16.f32 "
        "{%0,%1,%2,%3}, {%4,%5,%6,%7}, {%8,%9}, {%0,%1,%2,%3};"
        : "+f"(c[0]), "+f"(c[1]), "+f"(c[2]), "+f"(c[3])
        : "r"(a[0]), "r"(a[1]), "r"(a[2]), "r"(a[3]), "r"(b0), "r"(b1));
}
__device__ __forceinline__ float tanh_approx(float x) {
    float r;
    asm("tanh.approx.f32 %0, %1;" : "=f"(r) : "f"(x));
    return r;
}

// ---------------------------------------------------------------------------
// Kernel 1: fused prep (node forward + Wf bf16 convert).
// Node part uses a TRANSPOSED state stage: s[col][row], column stride 20
// floats (80 B, 16B-aligned; 20*ix mod 32 spans 8 bank residues), so each
// per-entry gather is ONE float4 covering 4 batch rows.
// ---------------------------------------------------------------------------
#define R_PER_BLK  16
#define SPAD       20                           // floats per column slot
#define NODE_BLKS  (BATCH / R_PER_BLK)          // 512
#define CONV_BLKS  (ACTION * N_NODES / 1024)    // 1024

__global__ __launch_bounds__(256) void prep_kernel(
    const float* __restrict__ state, const float* __restrict__ W,
    const float* __restrict__ b,     const int*   __restrict__ idx,
    const float* __restrict__ Wf)
{
    if (blockIdx.x >= NODE_BLKS) {
        const int i = ((blockIdx.x - NODE_BLKS) * 256 + threadIdx.x) * 4;
        float4 v = *(const float4*)(Wf + i);
        __nv_bfloat162* p = (__nv_bfloat162*)(g_wf + i);
        p[0] = __floats2bfloat162_rn(v.x, v.y);
        p[1] = __floats2bfloat162_rn(v.z, v.w);
        return;
    }
    __shared__ float s[STATE_DIM * SPAD];       // 25.8 KB, transposed
    const int t = threadIdx.x, row0 = blockIdx.x * R_PER_BLK;
    const float* sp = state + (long)row0 * STATE_DIM;
    // transpose into smem: s[col*SPAD + row] = state[row0+row][col]
    for (int i = t; i < R_PER_BLK * STATE_DIM; i += 256) {
        const int row = i / STATE_DIM, col = i - row * STATE_DIM;
        s[col * SPAD + row] = sp[i];
    }

    float w[ENTRIES]; int ix[ENTRIES];
#pragma unroll
    for (int e = 0; e < ENTRIES; e++) { w[e] = W[t*ENTRIES+e]; ix[e] = idx[t*ENTRIES+e]; }
    const float bb = b[t];
    __syncthreads();

    float4 acc[4];
#pragma unroll
    for (int j = 0; j < 4; j++) acc[j] = make_float4(bb, bb, bb, bb);

#pragma unroll
    for (int e = 0; e < ENTRIES; e++) {
        const float4* col = (const float4*)&s[ix[e] * SPAD];
        const float we = w[e];
#pragma unroll
        for (int j = 0; j < 4; j++) {
            float4 v = col[j];
            acc[j].x = fmaf(v.x, we, acc[j].x);
            acc[j].y = fmaf(v.y, we, acc[j].y);
            acc[j].z = fmaf(v.z, we, acc[j].z);
            acc[j].w = fmaf(v.w, we, acc[j].w);
        }
    }
    const float* af = (const float*)acc;
#pragma unroll
    for (int r = 0; r < R_PER_BLK; r++)
        g_y[(long)(row0 + r) * N_NODES + t] = __float2bfloat16(tanh_approx(af[r]));
}

// ---------------------------------------------------------------------------
// Kernel 2 (R11 exact): out = 500*sigmoid(y @ Wf^T), bf16 mma.sync.m16n8k16.
// CTA tile 128x128, 256 threads (8 warps, 2m x 4n), warp tile 64x32.
// 3-stage cp.async pipeline over the 4 K-chunks, 2 CTAs/SM.
// Smem rows padded to 144 B (stride ≡ 4 mod 32 words: conflict-free).
// ---------------------------------------------------------------------------
#define BK      64
#define ROWB    144                    // 72 bf16 per row
#define TILE_A  (128 * ROWB)           // 18432 B
#define STAGE_B (2 * TILE_A)           // A + B = 36864 B
#define NSTAGE  3
#define SMEM_SZ (NSTAGE * STAGE_B)     // 110592 B

__global__ __launch_bounds__(256, 2) void gemm_sig_kernel(float* __restrict__ out)
{
    extern __shared__ char smem[];
    const uint32_t sb = smem_u32(smem);
    const int tid    = threadIdx.x;
    const int lane   = tid & 31;
    const int wid    = tid >> 5;
    const int warp_m = wid >> 2;       // 0..1
    const int warp_n = wid & 3;        // 0..3
    const int n0 = blockIdx.x * 128;
    const int m0 = blockIdx.y * 128;

    const __nv_bfloat16* gA = g_y  + (size_t)m0 * N_NODES;
    const __nv_bfloat16* gB = g_wf + (size_t)n0 * N_NODES;

    float acc[4][4][4] = {};

    uint32_t a_base[4];
#pragma unroll
    for (int mt = 0; mt < 4; mt++)
        a_base[mt] = sb + (warp_m * 64 + mt * 16 + (lane & 15)) * ROWB + (lane >> 4) * 16;
    uint32_t b_base[2];
#pragma unroll
    for (int p = 0; p < 2; p++)
        b_base[p] = sb + TILE_A
                  + (warp_n * 32 + p * 16 + ((lane >> 4) & 1) * 8 + (lane & 7)) * ROWB
                  + ((lane >> 3) & 1) * 16;

    // ---- prologue: issue stages 0,1,2 (k0 = 0, 64, 128)
#pragma unroll
    for (int s = 0; s < 3; s++) {
        const uint32_t dst = sb + s * STAGE_B;
        const int k0 = s * BK;
#pragma unroll
        for (int i = 0; i < 4; i++) {
            const int e = tid + i * 256, r = e >> 3, c = e & 7;
            const uint32_t so = r * ROWB + c * 16;
            CP_ASYNC16(dst + so,          (const void*)(gA + (size_t)r * N_NODES + k0 + c * 8));
            CP_ASYNC16(dst + TILE_A + so, (const void*)(gB + (size_t)r * N_NODES + k0 + c * 8));
        }
        CP_COMMIT();
    }

#pragma unroll
    for (int it = 0; it < 4; it++) {
        if (it == 0)      CP_WAIT(2);
        else if (it == 1) CP_WAIT(2);
        else if (it == 2) CP_WAIT(1);
        else              CP_WAIT(0);
        __syncthreads();

        const uint32_t soff = (it % NSTAGE) * STAGE_B;
#pragma unroll
        for (int kc = 0; kc < 4; kc++) {
            uint32_t a[4][4], bp[2][4];
#pragma unroll
            for (int mt = 0; mt < 4; mt++) ldmx4(a[mt], a_base[mt] + soff + kc * 32);
#pragma unroll
            for (int p = 0; p < 2; p++)    ldmx4(bp[p], b_base[p]  + soff + kc * 32);
#pragma unroll
            for (int mt = 0; mt < 4; mt++)
#pragma unroll
                for (int nt = 0; nt < 4; nt++)
                    mma_bf16(acc[mt][nt], a[mt],
                             bp[nt >> 1][(nt & 1) * 2], bp[nt >> 1][(nt & 1) * 2 + 1]);
        }

        if (it == 0) {
            __syncthreads();
            const uint32_t dst = sb;          // buffer 0 now free
            const int k0 = 3 * BK;
#pragma unroll
            for (int i = 0; i < 4; i++) {
                const int e = tid + i * 256, r = e >> 3, c = e & 7;
                const uint32_t so = r * ROWB + c * 16;
                CP_ASYNC16(dst + so,          (const void*)(gA + (size_t)r * N_NODES + k0 + c * 8));
                CP_ASYNC16(dst + TILE_A + so, (const void*)(gB + (size_t)r * N_NODES + k0 + c * 8));
            }
            CP_COMMIT();
        }
    }

    // Epilogue: 500*sigmoid via MUFU rcp.
    const int frow = lane >> 2, fcol = lane & 3;
#pragma unroll
    for (int mt = 0; mt < 4; mt++) {
        const int m = m0 + warp_m * 64 + mt * 16 + frow;
#pragma unroll
        for (int nt = 0; nt < 4; nt++) {
            const int n = n0 + warp_n * 32 + nt * 8 + 2 * fcol;
            float2 o0, o1;
            o0.x = __fdividef(500.0f, 1.0f + __expf(-acc[mt][nt][0]));
            o0.y = __fdividef(500.0f, 1.0f + __expf(-acc[mt][nt][1]));
            o1.x = __fdividef(500.0f, 1.0f + __expf(-acc[mt][nt][2]));
            o1.y = __fdividef(500.0f, 1.0f + __expf(-acc[mt][nt][3]));
            *(float2*)&out[(size_t)m * ACTION + n]       = o0;
            *(float2*)&out[(size_t)(m + 8) * ACTION + n] = o1;
        }
    }
}

// ---------------------------------------------------------------------------
extern "C" void kernel_launch(void* const* d_in, const int* in_sizes, int n_in,
                              void* d_out, int out_size)
{
    const float* state = (const float*)d_in[0];
    const float* W     = (const float*)d_in[1];
    const float* b     = (const float*)d_in[2];
    const float* Wf    = (const float*)d_in[3];
    const int*   idx   = (const int*)  d_in[4];
    float*       out   = (float*)d_out;

    cudaFuncSetAttribute(gemm_sig_kernel,
                         cudaFuncAttributeMaxDynamicSharedMemorySize, SMEM_SZ);

    prep_kernel<<<NODE_BLKS + CONV_BLKS, 256>>>(state, W, b, idx, Wf);

    dim3 grid(ACTION / 128, BATCH / 128);
    gemm_sig_kernel<<<grid, 256, SMEM_SZ>>>(out);
}

// round 16
// speedup vs baseline: 1.5045x; 1.0706x over previous
#include <cuda_runtime.h>
#include <cuda_bf16.h>
#include <cstdint>

#define BATCH      8192
#define STATE_DIM  322
#define N_NODES    256
#define ENTRIES    27
#define ACTION     4096

// Intermediates: y as bf16 [BATCH][256] (4 MB), Wf as bf16 [4096][256] (2 MB)
__device__ __nv_bfloat16 g_y [BATCH  * N_NODES];
__device__ __nv_bfloat16 g_wf[ACTION * N_NODES];

__device__ __forceinline__ uint32_t smem_u32(const void* p) {
    uint32_t a;
    asm("{ .reg .u64 t; cvta.to.shared.u64 t, %1; cvt.u32.u64 %0, t; }" : "=r"(a) : "l"(p));
    return a;
}
#define CP_ASYNC16(dst, src) \
    asm volatile("cp.async.cg.shared.global [%0], [%1], 16;" :: "r"(dst), "l"(src))
#define CP_COMMIT()  asm volatile("cp.async.commit_group;" ::: "memory")
#define CP_WAIT(N)   asm volatile("cp.async.wait_group %0;" :: "n"(N) : "memory")

__device__ __forceinline__ void ldmx4(uint32_t* r, uint32_t addr) {
    asm volatile("ldmatrix.sync.aligned.m8n8.x4.shared.b16 {%0,%1,%2,%3}, [%4];"
                 : "=r"(r[0]), "=r"(r[1]), "=r"(r[2]), "=r"(r[3]) : "r"(addr));
}
__device__ __forceinline__ void mma_bf16(float c[4], const uint32_t a[4],
                                         uint32_t b0, uint32_t b1) {
    asm volatile(
        "mma.sync.aligned.m16n8k16.row.col.f32.bf16.bf16.f32 "
        "{%0,%1,%2,%3}, {%4,%5,%6,%7}, {%8,%9}, {%0,%1,%2,%3};"
        : "+f"(c[0]), "+f"(c[1]), "+f"(c[2]), "+f"(c[3])
        : "r"(a[0]), "r"(a[1]), "r"(a[2]), "r"(a[3]), "r"(b0), "r"(b1));
}
__device__ __forceinline__ float tanh_approx(float x) {
    float r;
    asm("tanh.approx.f32 %0, %1;" : "=f"(r) : "f"(x));
    return r;
}
// 500*sigmoid(x) = 250 + 250*tanh(x/2): one MUFU + FMAs (vs EX2+RCP chain)
__device__ __forceinline__ float sig500(float x) {
    return fmaf(250.0f, tanh_approx(0.5f * x), 250.0f);
}

// ---------------------------------------------------------------------------
// Kernel 1: fused prep (node forward + Wf bf16 convert)  [R11 proven form]
// ---------------------------------------------------------------------------
#define R_PER_BLK  16
#define NODE_BLKS  (BATCH / R_PER_BLK)          // 512
#define CONV_BLKS  (ACTION * N_NODES / 1024)    // 1024

__global__ __launch_bounds__(256) void prep_kernel(
    const float* __restrict__ state, const float* __restrict__ W,
    const float* __restrict__ b,     const int*   __restrict__ idx,
    const float* __restrict__ Wf)
{
    if (blockIdx.x >= NODE_BLKS) {
        const int i = ((blockIdx.x - NODE_BLKS) * 256 + threadIdx.x) * 4;
        float4 v = *(const float4*)(Wf + i);
        __nv_bfloat162* p = (__nv_bfloat162*)(g_wf + i);
        p[0] = __floats2bfloat162_rn(v.x, v.y);
        p[1] = __floats2bfloat162_rn(v.z, v.w);
        return;
    }
    __shared__ float s[R_PER_BLK * STATE_DIM];
    const int t = threadIdx.x, row0 = blockIdx.x * R_PER_BLK;
    const float* sp = state + (long)row0 * STATE_DIM;
    for (int i = t; i < R_PER_BLK * STATE_DIM; i += 256) s[i] = sp[i];

    float w[ENTRIES]; int ix[ENTRIES];
#pragma unroll
    for (int e = 0; e < ENTRIES; e++) { w[e] = W[t*ENTRIES+e]; ix[e] = idx[t*ENTRIES+e]; }
    const float bb = b[t];
    __syncthreads();
#pragma unroll 4
    for (int r = 0; r < R_PER_BLK; r++) {
        const float* sr = s + r * STATE_DIM;
        float acc = bb;
#pragma unroll
        for (int e = 0; e < ENTRIES; e++) acc = fmaf(sr[ix[e]], w[e], acc);
        g_y[(long)(row0 + r) * N_NODES + t] = __float2bfloat16(tanh_approx(acc));
    }
}

// ---------------------------------------------------------------------------
// Kernel 2 (R11 structure): out = 500*sigmoid(y @ Wf^T), bf16 m16n8k16.
// CTA tile 128x128, 256 threads (8 warps 2m x 4n), warp tile 64x32.
// 3-stage cp.async pipeline over the 4 K-chunks, 2 CTAs/SM.
// Smem rows padded to 144 B (stride ≡ 4 mod 32 words: conflict-free).
// Epilogue via single tanh.approx MUFU per element.
// ---------------------------------------------------------------------------
#define BK      64
#define ROWB    144                    // 72 bf16 per row
#define TILE_A  (128 * ROWB)           // 18432 B
#define STAGE_B (2 * TILE_A)           // A + B = 36864 B
#define NSTAGE  3
#define SMEM_SZ (NSTAGE * STAGE_B)     // 110592 B

__global__ __launch_bounds__(256, 2) void gemm_sig_kernel(float* __restrict__ out)
{
    extern __shared__ char smem[];
    const uint32_t sb = smem_u32(smem);
    const int tid    = threadIdx.x;
    const int lane   = tid & 31;
    const int wid    = tid >> 5;
    const int warp_m = wid >> 2;       // 0..1
    const int warp_n = wid & 3;        // 0..3
    const int n0 = blockIdx.x * 128;
    const int m0 = blockIdx.y * 128;

    const __nv_bfloat16* gA = g_y  + (size_t)m0 * N_NODES;
    const __nv_bfloat16* gB = g_wf + (size_t)n0 * N_NODES;

    float acc[4][4][4] = {};

    uint32_t a_base[4];
#pragma unroll
    for (int mt = 0; mt < 4; mt++)
        a_base[mt] = sb + (warp_m * 64 + mt * 16 + (lane & 15)) * ROWB + (lane >> 4) * 16;
    uint32_t b_base[2];
#pragma unroll
    for (int p = 0; p < 2; p++)
        b_base[p] = sb + TILE_A
                  + (warp_n * 32 + p * 16 + ((lane >> 4) & 1) * 8 + (lane & 7)) * ROWB
                  + ((lane >> 3) & 1) * 16;

    // ---- prologue: issue stages 0,1,2 (k0 = 0, 64, 128)
#pragma unroll
    for (int s = 0; s < 3; s++) {
        const uint32_t dst = sb + s * STAGE_B;
        const int k0 = s * BK;
#pragma unroll
        for (int i = 0; i < 4; i++) {
            const int e = tid + i * 256, r = e >> 3, c = e & 7;
            const uint32_t so = r * ROWB + c * 16;
            CP_ASYNC16(dst + so,          (const void*)(gA + (size_t)r * N_NODES + k0 + c * 8));
            CP_ASYNC16(dst + TILE_A + so, (const void*)(gB + (size_t)r * N_NODES + k0 + c * 8));
        }
        CP_COMMIT();
    }

#pragma unroll
    for (int it = 0; it < 4; it++) {
        if (it == 0)      CP_WAIT(2);
        else if (it == 1) CP_WAIT(2);
        else if (it == 2) CP_WAIT(1);
        else              CP_WAIT(0);
        __syncthreads();

        const uint32_t soff = (it % NSTAGE) * STAGE_B;
#pragma unroll
        for (int kc = 0; kc < 4; kc++) {
            uint32_t a[4][4], bp[2][4];
#pragma unroll
            for (int mt = 0; mt < 4; mt++) ldmx4(a[mt], a_base[mt] + soff + kc * 32);
#pragma unroll
            for (int p = 0; p < 2; p++)    ldmx4(bp[p], b_base[p]  + soff + kc * 32);
#pragma unroll
            for (int mt = 0; mt < 4; mt++)
#pragma unroll
                for (int nt = 0; nt < 4; nt++)
                    mma_bf16(acc[mt][nt], a[mt],
                             bp[nt >> 1][(nt & 1) * 2], bp[nt >> 1][(nt & 1) * 2 + 1]);
        }

        if (it == 0) {
            __syncthreads();
            const uint32_t dst = sb;          // buffer 0 now free
            const int k0 = 3 * BK;
#pragma unroll
            for (int i = 0; i < 4; i++) {
                const int e = tid + i * 256, r = e >> 3, c = e & 7;
                const uint32_t so = r * ROWB + c * 16;
                CP_ASYNC16(dst + so,          (const void*)(gA + (size_t)r * N_NODES + k0 + c * 8));
                CP_ASYNC16(dst + TILE_A + so, (const void*)(gB + (size_t)r * N_NODES + k0 + c * 8));
            }
            CP_COMMIT();
        }
    }

    // Epilogue: 500*sigmoid = 250 + 250*tanh(x/2), one MUFU per element.
    const int frow = lane >> 2, fcol = lane & 3;
#pragma unroll
    for (int mt = 0; mt < 4; mt++) {
        const int m = m0 + warp_m * 64 + mt * 16 + frow;
#pragma unroll
        for (int nt = 0; nt < 4; nt++) {
            const int n = n0 + warp_n * 32 + nt * 8 + 2 * fcol;
            float2 o0, o1;
            o0.x = sig500(acc[mt][nt][0]);
            o0.y = sig500(acc[mt][nt][1]);
            o1.x = sig500(acc[mt][nt][2]);
            o1.y = sig500(acc[mt][nt][3]);
            *(float2*)&out[(size_t)m * ACTION + n]       = o0;
            *(float2*)&out[(size_t)(m + 8) * ACTION + n] = o1;
        }
    }
}

// ---------------------------------------------------------------------------
extern "C" void kernel_launch(void* const* d_in, const int* in_sizes, int n_in,
                              void* d_out, int out_size)
{
    const float* state = (const float*)d_in[0];
    const float* W     = (const float*)d_in[1];
    const float* b     = (const float*)d_in[2];
    const float* Wf    = (const float*)d_in[3];
    const int*   idx   = (const int*)  d_in[4];
    float*       out   = (float*)d_out;

    cudaFuncSetAttribute(gemm_sig_kernel,
                         cudaFuncAttributeMaxDynamicSharedMemorySize, SMEM_SZ);

    prep_kernel<<<NODE_BLKS + CONV_BLKS, 256>>>(state, W, b, idx, Wf);

    dim3 grid(ACTION / 128, BATCH / 128);
    gemm_sig_kernel<<<grid, 256, SMEM_SZ>>>(out);
}